// round 10
// baseline (speedup 1.0000x reference)
#include <cuda_runtime.h>
#include <cstdint>
#include <math.h>

#define K_DIM 1024
#define N_EXPERTS 64
#define BM 64
#define KCHUNK 32
#define NCHUNK 32
#define ROW_STRIDE 68                        // 64 + 4 pad (floats)
#define STAGE_FLOATS (2 * KCHUNK * ROW_STRIDE)   // xs + ws, 4352 floats
#define SMEM_BYTES (2 * STAGE_FLOATS * 4)        // 34816
#define FULL 0xffffffffu

__global__ __launch_bounds__(128, 4)
void router_ffma_kernel(const float* __restrict__ x,
                        const float* __restrict__ Wm,
                        const float* __restrict__ bias,
                        float* __restrict__ out,
                        int num_tokens) {
    extern __shared__ float smem[];   // [stage][k][xs row 0..63 | ws row 0..63]
    const int tid = threadIdx.x;
    const int bm  = blockIdx.x * BM;

    // loader mapping: thread (r, h): r = row 0..63, h = k-half 0..1
    const int r = tid & 63;
    const int h = tid >> 6;

    // compute mapping: thread = (tym 0..15 token-group, txk 0..7 expert-group)
    const int txk = tid & 7;
    const int tym = tid >> 3;

    float4 xv[4], wv[4];
    auto ldg_chunk = [&](int c) {
        const float* gx = x + (size_t)(bm + r) * K_DIM + c * KCHUNK + h * 16;
        #pragma unroll
        for (int j = 0; j < 4; ++j)
            xv[j] = __ldg((const float4*)(gx + j * 4));
        const float* gw = Wm + (size_t)r * K_DIM + c * KCHUNK + h * 16;
        #pragma unroll
        for (int j = 0; j < 4; ++j)
            wv[j] = __ldg((const float4*)(gw + j * 4));
    };
    auto sts_chunk = [&](int buf) {
        float* xs = smem + buf * STAGE_FLOATS;            // [k][ROW_STRIDE]
        float* ws = xs + KCHUNK * ROW_STRIDE;
        #pragma unroll
        for (int j = 0; j < 4; ++j) {
            const int k = h * 16 + j * 4;
            xs[(k + 0) * ROW_STRIDE + r] = xv[j].x;
            xs[(k + 1) * ROW_STRIDE + r] = xv[j].y;
            xs[(k + 2) * ROW_STRIDE + r] = xv[j].z;
            xs[(k + 3) * ROW_STRIDE + r] = xv[j].w;
            ws[(k + 0) * ROW_STRIDE + r] = wv[j].x;
            ws[(k + 1) * ROW_STRIDE + r] = wv[j].y;
            ws[(k + 2) * ROW_STRIDE + r] = wv[j].z;
            ws[(k + 3) * ROW_STRIDE + r] = wv[j].w;
        }
    };

    float acc[4][8];
    #pragma unroll
    for (int i = 0; i < 4; ++i)
        #pragma unroll
        for (int j = 0; j < 8; ++j) acc[i][j] = 0.0f;

    ldg_chunk(0);
    sts_chunk(0);
    __syncthreads();

    #pragma unroll 1
    for (int c = 0; c < NCHUNK; ++c) {
        if (c + 1 < NCHUNK) ldg_chunk(c + 1);

        const float* xs = smem + (c & 1) * STAGE_FLOATS;
        const float* ws = xs + KCHUNK * ROW_STRIDE;

        #pragma unroll 8
        for (int k = 0; k < KCHUNK; ++k) {
            const float4 a  = *(const float4*)&xs[k * ROW_STRIDE + tym * 4];
            const float4 b0 = *(const float4*)&ws[k * ROW_STRIDE + txk * 8];
            const float4 b1 = *(const float4*)&ws[k * ROW_STRIDE + txk * 8 + 4];
            const float am[4] = {a.x, a.y, a.z, a.w};
            const float bn[8] = {b0.x, b0.y, b0.z, b0.w, b1.x, b1.y, b1.z, b1.w};
            #pragma unroll
            for (int i = 0; i < 4; ++i)
                #pragma unroll
                for (int j = 0; j < 8; ++j)
                    acc[i][j] = fmaf(am[i], bn[j], acc[i][j]);
        }
        __syncthreads();
        if (c + 1 < NCHUNK) {
            sts_chunk((c + 1) & 1);
            __syncthreads();
        }
    }

    // ---- dump logits to smem (aliases stage buffers; 64 x 68 floats) ----
    float* lg = smem;
    #pragma unroll
    for (int i = 0; i < 4; ++i)
        #pragma unroll
        for (int j = 0; j < 8; ++j)
            lg[(tym * 4 + i) * ROW_STRIDE + txk * 8 + j] = acc[i][j];
    __syncthreads();
    if (tid >= BM) return;

    // ---- exact epilogue: thread tid owns token bm+tid ----
    const float4* b4 = (const float4*)bias;
    const float4* lrow = (const float4*)&lg[tid * ROW_STRIDE];

    float m1 = -INFINITY, m2 = -INFINITY;
    int i1 = 0, i2 = 0;
    float v[64];
    #pragma unroll
    for (int q = 0; q < 16; ++q) {
        const float4 lv = lrow[q];
        const float4 bv = __ldg(b4 + q);
        v[q * 4 + 0] = lv.x + bv.x;
        v[q * 4 + 1] = lv.y + bv.y;
        v[q * 4 + 2] = lv.z + bv.z;
        v[q * 4 + 3] = lv.w + bv.w;
    }
    #pragma unroll
    for (int e = 0; e < 64; ++e) {
        if (v[e] > m1) { m2 = m1; i2 = i1; m1 = v[e]; i1 = e; }
        else if (v[e] > m2) { m2 = v[e]; i2 = e; }
    }
    float s = 0.0f;
    #pragma unroll
    for (int e = 0; e < 64; ++e) s += __expf(v[e] - m1);

    const float inv = 1.0f / s;
    const int tk = bm + tid;
    float* oid = out + (size_t)num_tokens * 2;
    *(float2*)&out[tk * 2] = make_float2(inv, __expf(m2 - m1) * inv);
    *(float2*)&oid[tk * 2] = make_float2((float)i1, (float)i2);
}

extern "C" void kernel_launch(void* const* d_in, const int* in_sizes, int n_in,
                              void* d_out, int out_size) {
    const float* x = (const float*)d_in[0];   // [8,4096,1024]
    const float* W = (const float*)d_in[1];   // [64,1024]
    const float* b = (const float*)d_in[2];   // [64]
    float* out = (float*)d_out;

    const int num_tokens = in_sizes[0] / K_DIM;   // 32768
    const int grid = num_tokens / BM;             // 512

    cudaFuncSetAttribute(router_ffma_kernel,
                         cudaFuncAttributeMaxDynamicSharedMemorySize, SMEM_BYTES);
    router_ffma_kernel<<<grid, 128, SMEM_BYTES>>>(x, W, b, out, num_tokens);
}

// round 11
// speedup vs baseline: 1.8972x; 1.8972x over previous
#include <cuda_runtime.h>
#include <cstdint>
#include <math.h>

#define K_DIM 1024
#define N_EXPERTS 64
#define BM 128
#define KCHUNK 16
#define NLOCAL 32                 // chunks per group (512 K each)
#define XS_STRIDE 132             // [k][token] floats
#define WS_STRIDE 68              // [k][expert] floats
#define XS_FLOATS (KCHUNK * XS_STRIDE)             // 2112
#define GRP_FLOATS (KCHUNK * (XS_STRIDE + WS_STRIDE))  // 3200
#define LG_STRIDE 68
#define SMEM_FLOATS 8704          // max(2*GRP_FLOATS=6400, 128*65=8320, 128*68=8704)
#define FULL 0xffffffffu

#define GBAR(id) asm volatile("bar.sync %0, 128;" :: "r"(id) : "memory")

__global__ __launch_bounds__(256, 2)
void router_splitk_kernel(const float* __restrict__ x,
                          const float* __restrict__ Wm,
                          const float* __restrict__ bias,
                          float* __restrict__ out,
                          int num_tokens) {
    extern __shared__ float smem[];
    const int tid  = threadIdx.x;
    const int gid  = tid >> 7;          // k-split group 0/1
    const int gtid = tid & 127;
    const int bm   = blockIdx.x * BM;
    const int kbase = gid * (K_DIM / 2);

    float* xs = smem + gid * GRP_FLOATS;         // [16][132]
    float* ws = xs + XS_FLOATS;                  // [16][68]

    // loader mapping: kq = k-granule 0..3, row = 0..31
    const int kq  = gtid & 3;
    const int row = gtid >> 2;

    // compute mapping (within group): txk = expert oct 0..7, tym = token oct 0..15
    const int txk = gtid & 7;
    const int tym = gtid >> 3;

    auto load_chunk = [&](int c) {
        const int ko = kbase + c * KCHUNK + kq * 4;
        float4 xv[4], wv[2];
        const float* gx = x + (size_t)(bm + row) * K_DIM + ko;
        #pragma unroll
        for (int i = 0; i < 4; ++i)
            xv[i] = __ldg((const float4*)(gx + (size_t)(32 * i) * K_DIM));
        const float* gw = Wm + (size_t)row * K_DIM + ko;
        #pragma unroll
        for (int i = 0; i < 2; ++i)
            wv[i] = __ldg((const float4*)(gw + (size_t)(32 * i) * K_DIM));
        #pragma unroll
        for (int i = 0; i < 4; ++i) {
            xs[(kq * 4 + 0) * XS_STRIDE + row + 32 * i] = xv[i].x;
            xs[(kq * 4 + 1) * XS_STRIDE + row + 32 * i] = xv[i].y;
            xs[(kq * 4 + 2) * XS_STRIDE + row + 32 * i] = xv[i].z;
            xs[(kq * 4 + 3) * XS_STRIDE + row + 32 * i] = xv[i].w;
        }
        #pragma unroll
        for (int i = 0; i < 2; ++i) {
            ws[(kq * 4 + 0) * WS_STRIDE + row + 32 * i] = wv[i].x;
            ws[(kq * 4 + 1) * WS_STRIDE + row + 32 * i] = wv[i].y;
            ws[(kq * 4 + 2) * WS_STRIDE + row + 32 * i] = wv[i].z;
            ws[(kq * 4 + 3) * WS_STRIDE + row + 32 * i] = wv[i].w;
        }
    };

    float acc[8][8];
    #pragma unroll
    for (int i = 0; i < 8; ++i)
        #pragma unroll
        for (int j = 0; j < 8; ++j) acc[i][j] = 0.0f;

    const int barid = 1 + gid;

    load_chunk(0);
    GBAR(barid);

    #pragma unroll 1
    for (int c = 0; c < NLOCAL; ++c) {
        #pragma unroll 4
        for (int k = 0; k < KCHUNK; ++k) {
            const float4 a0 = *(const float4*)&xs[k * XS_STRIDE + tym * 8];
            const float4 a1 = *(const float4*)&xs[k * XS_STRIDE + tym * 8 + 4];
            const float4 b0 = *(const float4*)&ws[k * WS_STRIDE + txk * 8];
            const float4 b1 = *(const float4*)&ws[k * WS_STRIDE + txk * 8 + 4];
            const float am[8] = {a0.x, a0.y, a0.z, a0.w, a1.x, a1.y, a1.z, a1.w};
            const float bn[8] = {b0.x, b0.y, b0.z, b0.w, b1.x, b1.y, b1.z, b1.w};
            #pragma unroll
            for (int i = 0; i < 8; ++i)
                #pragma unroll
                for (int j = 0; j < 8; ++j)
                    acc[i][j] = fmaf(am[i], bn[j], acc[i][j]);
        }
        GBAR(barid);
        if (c + 1 < NLOCAL) {
            load_chunk(c + 1);
            GBAR(barid);
        }
    }

    // ---- merge k-split partials ----
    __syncthreads();
    if (gid == 1) {
        #pragma unroll
        for (int i = 0; i < 8; ++i)
            #pragma unroll
            for (int j = 0; j < 8; ++j)
                smem[gtid * 65 + i * 8 + j] = acc[i][j];
    }
    __syncthreads();
    if (gid != 0) return;

    #pragma unroll
    for (int i = 0; i < 8; ++i)
        #pragma unroll
        for (int j = 0; j < 8; ++j)
            acc[i][j] += smem[gtid * 65 + i * 8 + j];
    GBAR(1);

    // ---- dump summed logits [token][expert] ----
    #pragma unroll
    for (int i = 0; i < 8; ++i)
        #pragma unroll
        for (int j = 0; j < 8; ++j)
            smem[(tym * 8 + i) * LG_STRIDE + txk * 8 + j] = acc[i][j];
    GBAR(1);

    // ---- exact per-token epilogue: thread gtid owns token bm+gtid ----
    const float4* b4 = (const float4*)bias;
    const float4* lrow = (const float4*)&smem[gtid * LG_STRIDE];

    float v[64];
    #pragma unroll
    for (int q = 0; q < 16; ++q) {
        const float4 lv = lrow[q];
        const float4 bv = __ldg(b4 + q);
        v[q * 4 + 0] = lv.x + bv.x;
        v[q * 4 + 1] = lv.y + bv.y;
        v[q * 4 + 2] = lv.z + bv.z;
        v[q * 4 + 3] = lv.w + bv.w;
    }
    float m1 = -INFINITY, m2 = -INFINITY;
    int i1 = 0, i2 = 0;
    #pragma unroll
    for (int e = 0; e < 64; ++e) {
        if (v[e] > m1) { m2 = m1; i2 = i1; m1 = v[e]; i1 = e; }
        else if (v[e] > m2) { m2 = v[e]; i2 = e; }
    }
    float s = 0.0f;
    #pragma unroll
    for (int e = 0; e < 64; ++e) s += __expf(v[e] - m1);

    const float inv = 1.0f / s;
    const int tk = bm + gtid;
    float* oid = out + (size_t)num_tokens * 2;
    *(float2*)&out[tk * 2] = make_float2(inv, __expf(m2 - m1) * inv);
    *(float2*)&oid[tk * 2] = make_float2((float)i1, (float)i2);
}

extern "C" void kernel_launch(void* const* d_in, const int* in_sizes, int n_in,
                              void* d_out, int out_size) {
    const float* x = (const float*)d_in[0];   // [8,4096,1024]
    const float* W = (const float*)d_in[1];   // [64,1024]
    const float* b = (const float*)d_in[2];   // [64]
    float* out = (float*)d_out;

    const int num_tokens = in_sizes[0] / K_DIM;   // 32768
    const int grid = num_tokens / BM;             // 256

    cudaFuncSetAttribute(router_splitk_kernel,
                         cudaFuncAttributeMaxDynamicSharedMemorySize, SMEM_FLOATS * 4);
    router_splitk_kernel<<<grid, 256, SMEM_FLOATS * 4>>>(x, W, b, out, num_tokens);
}